// round 8
// baseline (speedup 1.0000x reference)
#include <cuda_runtime.h>

#define NROWS 128
#define LEN   2048
#define NK    6
#define NT    512

__device__ float        g_partials[NROWS];
__device__ unsigned int g_count = 0;

__device__ __forceinline__ float4 f4add(float4 a, float4 b) {
    return make_float4(a.x + b.x, a.y + b.y, a.z + b.z, a.w + b.w);
}

__global__ void __launch_bounds__(NT, 1) entropy_fused(
    const float* __restrict__ in, const float* __restrict__ tg, float* __restrict__ out)
{
    // P[i] = inclusive prefix over elements < i of (e^a, a e^a, e^b, b e^b)
    __shared__ float4 P[LEN + 1];
    __shared__ float4 wtot[NT / 32];
    __shared__ float  redk[NT / 32];
    __shared__ int    lastFlag;

    const int tid  = threadIdx.x;
    const int lane = tid & 31, wid = tid >> 5;
    const int row  = blockIdx.x;

    // ---- 4 consecutive elements per thread (one LDG.128 per tensor) ----
    const float4 a4 = ((const float4*)(in + (size_t)row * LEN))[tid];
    const float4 b4 = ((const float4*)(tg + (size_t)row * LEN))[tid];
    float4 v[4];
    {
        const float ax[4] = {a4.x, a4.y, a4.z, a4.w};
        const float bx[4] = {b4.x, b4.y, b4.z, b4.w};
        float4 run = make_float4(0.f, 0.f, 0.f, 0.f);
        #pragma unroll
        for (int j = 0; j < 4; j++) {
            float ea = __expf(ax[j]);
            float eb = __expf(bx[j]);
            run.x += ea;  run.y += ax[j] * ea;
            run.z += eb;  run.w += bx[j] * eb;
            v[j] = run;
        }
    }

    // warp inclusive scan of per-thread totals
    float4 t = v[3];
    #pragma unroll
    for (int off = 1; off < 32; off <<= 1) {
        float4 n;
        n.x = __shfl_up_sync(0xffffffffu, t.x, off);
        n.y = __shfl_up_sync(0xffffffffu, t.y, off);
        n.z = __shfl_up_sync(0xffffffffu, t.z, off);
        n.w = __shfl_up_sync(0xffffffffu, t.w, off);
        if (lane >= off) t = f4add(t, n);
    }
    if (lane == 31) wtot[wid] = t;
    __syncthreads();
    if (wid == 0) {                 // scan 16 warp totals
        float4 w = (lane < NT / 32) ? wtot[lane] : make_float4(0.f, 0.f, 0.f, 0.f);
        #pragma unroll
        for (int off = 1; off < NT / 32; off <<= 1) {
            float4 n;
            n.x = __shfl_up_sync(0xffffffffu, w.x, off);
            n.y = __shfl_up_sync(0xffffffffu, w.y, off);
            n.z = __shfl_up_sync(0xffffffffu, w.z, off);
            n.w = __shfl_up_sync(0xffffffffu, w.w, off);
            if (lane >= off) w = f4add(w, n);
        }
        if (lane < NT / 32) wtot[lane] = w;
    }
    __syncthreads();
    {
        float4 woff = (wid > 0) ? wtot[wid - 1] : make_float4(0.f, 0.f, 0.f, 0.f);
        float4 ex = make_float4(woff.x + t.x - v[3].x, woff.y + t.y - v[3].y,
                                woff.z + t.z - v[3].z, woff.w + t.w - v[3].w);
        #pragma unroll
        for (int j = 0; j < 4; j++) P[4 * tid + 1 + j] = f4add(v[j], ex);
        if (tid == 0) P[0] = make_float4(0.f, 0.f, 0.f, 0.f);
    }
    __syncthreads();

    // ---- windows: 24 straight-line bodies (4 s-positions x 6 k) ----
    // lo operands hoisted once per s-position; only j=3 needs a validity check.
    // ent1 - ent2 = (S1*Z2 - S2*Z1)*r - log(Z1^2 * r), r = 1/(Z1*Z2)
    float4 lo[4];
    #pragma unroll
    for (int j = 0; j < 4; j++) lo[j] = P[tid + j * NT];
    float acc = 0.0f;
    #pragma unroll
    for (int kk = 0; kk < NK; kk++) {
        const int   k  = 4 << kk;
        const int   nW = LEN - k + 1;            // 2045..1921; tid+2*NT=1535 < nW always
        const float wk = 1.0f / (128.0f * (float)nW);
        float acck = 0.0f;
        #pragma unroll
        for (int j = 0; j < 4; j++) {
            const int s = tid + j * NT;
            if (j < 3 || s < nW) {
                float4 hi = P[s + k];
                float z1 = hi.x - lo[j].x, f1 = hi.y - lo[j].y;
                float z2 = hi.z - lo[j].z, f2 = hi.w - lo[j].w;
                float r = __fdividef(1.0f, z1 * z2);
                float d = fmaf(f1 * z2 - f2 * z1, r, -__logf(z1 * z1 * r));
                acck += fabsf(d);
            }
        }
        acc = fmaf(acck, wk, acc);
    }

    // ---- block reduce ----
    #pragma unroll
    for (int off = 16; off; off >>= 1) acc += __shfl_down_sync(0xffffffffu, acc, off);
    if (lane == 0) redk[wid] = acc;
    __syncthreads();
    if (wid == 0) {
        float s = (lane < NT / 32) ? redk[lane] : 0.0f;
        #pragma unroll
        for (int off = NT / 64; off; off >>= 1) s += __shfl_down_sync(0xffffffffu, s, off);
        if (lane == 0) {
            g_partials[row] = s;
            __threadfence();
            unsigned prev = atomicAdd(&g_count, 1u);
            lastFlag = (prev == NROWS - 1);
        }
    }
    __syncthreads();

    // ---- last block: deterministic fixed-order final sum ----
    if (lastFlag) {
        volatile const float* vp = g_partials;
        if (wid == 0) {
            double s = 0.0;
            for (int i = lane; i < NROWS; i += 32) s += (double)vp[i];
            #pragma unroll
            for (int off = 16; off; off >>= 1) s += __shfl_down_sync(0xffffffffu, s, off);
            if (lane == 0) { out[0] = (float)s; g_count = 0; }
        }
    }
}

extern "C" void kernel_launch(void* const* d_in, const int* in_sizes, int n_in,
                              void* d_out, int out_size) {
    const float* in = (const float*)d_in[0];
    const float* tg = (const float*)d_in[1];
    entropy_fused<<<NROWS, NT>>>(in, tg, (float*)d_out);
}

// round 9
// speedup vs baseline: 1.2043x; 1.2043x over previous
#include <cuda_runtime.h>

#define NROWS 128
#define LEN   2048
#define NK    6
#define NT    512
#define NWARP (NT / 32)
#define FIXSCALE 1099511627776.0f        // 2^40
#define CNT_ONE  (1ull << 56)
#define SUM_MASK (CNT_ONE - 1ull)

// bits [56..63]: completed-block count; bits [0..55]: fixed-point (2^-40) loss sum.
// Zero-initialized at load; last block resets it each launch.
__device__ unsigned long long g_accum = 0ull;

__device__ __forceinline__ float4 f4add(float4 a, float4 b) {
    return make_float4(a.x + b.x, a.y + b.y, a.z + b.z, a.w + b.w);
}

__global__ void __launch_bounds__(NT, 1) entropy_fused(
    const float* __restrict__ in, const float* __restrict__ tg, float* __restrict__ out)
{
    // P[i] = inclusive prefix over elements < i of (e^a, a e^a, e^b, b e^b)
    __shared__ float4 P[LEN + 1];
    __shared__ float4 wtot[NWARP];
    __shared__ float  redk[NWARP];

    const int tid  = threadIdx.x;
    const int lane = tid & 31, wid = tid >> 5;
    const int row  = blockIdx.x;

    // ---- 4 consecutive elements per thread (one LDG.128 per tensor) ----
    const float4 a4 = ((const float4*)(in + (size_t)row * LEN))[tid];
    const float4 b4 = ((const float4*)(tg + (size_t)row * LEN))[tid];
    float4 v[4];
    {
        const float ax[4] = {a4.x, a4.y, a4.z, a4.w};
        const float bx[4] = {b4.x, b4.y, b4.z, b4.w};
        float4 run = make_float4(0.f, 0.f, 0.f, 0.f);
        #pragma unroll
        for (int j = 0; j < 4; j++) {
            float ea = __expf(ax[j]);
            float eb = __expf(bx[j]);
            run.x += ea;  run.y += ax[j] * ea;
            run.z += eb;  run.w += bx[j] * eb;
            v[j] = run;
        }
    }

    // warp inclusive scan of per-thread totals
    float4 t = v[3];
    #pragma unroll
    for (int off = 1; off < 32; off <<= 1) {
        float4 n;
        n.x = __shfl_up_sync(0xffffffffu, t.x, off);
        n.y = __shfl_up_sync(0xffffffffu, t.y, off);
        n.z = __shfl_up_sync(0xffffffffu, t.z, off);
        n.w = __shfl_up_sync(0xffffffffu, t.w, off);
        if (lane >= off) t = f4add(t, n);
    }
    if (lane == 31) wtot[wid] = t;
    __syncthreads();

    // EVERY warp scans the 16 warp totals (no second barrier, no warp0 serialization)
    float4 woff;
    {
        float4 w = (lane < NWARP) ? wtot[lane] : make_float4(0.f, 0.f, 0.f, 0.f);
        #pragma unroll
        for (int off = 1; off < NWARP; off <<= 1) {
            float4 n;
            n.x = __shfl_up_sync(0xffffffffu, w.x, off);
            n.y = __shfl_up_sync(0xffffffffu, w.y, off);
            n.z = __shfl_up_sync(0xffffffffu, w.z, off);
            n.w = __shfl_up_sync(0xffffffffu, w.w, off);
            if (lane >= off && lane < NWARP) w = f4add(w, n);
        }
        const int src = (wid > 0) ? wid - 1 : 0;
        woff.x = __shfl_sync(0xffffffffu, w.x, src);
        woff.y = __shfl_sync(0xffffffffu, w.y, src);
        woff.z = __shfl_sync(0xffffffffu, w.z, src);
        woff.w = __shfl_sync(0xffffffffu, w.w, src);
        if (wid == 0) woff = make_float4(0.f, 0.f, 0.f, 0.f);
    }
    {
        float4 ex = make_float4(woff.x + t.x - v[3].x, woff.y + t.y - v[3].y,
                                woff.z + t.z - v[3].z, woff.w + t.w - v[3].w);
        #pragma unroll
        for (int j = 0; j < 4; j++) P[4 * tid + 1 + j] = f4add(v[j], ex);
        if (tid == 0) P[0] = make_float4(0.f, 0.f, 0.f, 0.f);
    }
    __syncthreads();

    // ---- windows: 24 straight-line bodies (4 s-positions x 6 k) ----
    // ent1 - ent2 = (S1*Z2 - S2*Z1)*r - log(Z1^2 * r), r = 1/(Z1*Z2)
    float4 lo[4];
    #pragma unroll
    for (int j = 0; j < 4; j++) lo[j] = P[tid + j * NT];
    float acc = 0.0f;
    #pragma unroll
    for (int kk = 0; kk < NK; kk++) {
        const int   k  = 4 << kk;
        const int   nW = LEN - k + 1;            // 2045..1921; tid+2*NT=1535 < nW always
        const float wk = 1.0f / (128.0f * (float)nW);
        float acck = 0.0f;
        #pragma unroll
        for (int j = 0; j < 4; j++) {
            const int s = tid + j * NT;
            if (j < 3 || s < nW) {
                float4 hi = P[s + k];
                float z1 = hi.x - lo[j].x, f1 = hi.y - lo[j].y;
                float z2 = hi.z - lo[j].z, f2 = hi.w - lo[j].w;
                float r = __fdividef(1.0f, z1 * z2);
                float d = fmaf(f1 * z2 - f2 * z1, r, -__logf(z1 * z1 * r));
                acck += fabsf(d);
            }
        }
        acc = fmaf(acck, wk, acc);
    }

    // ---- block reduce ----
    #pragma unroll
    for (int off = 16; off; off >>= 1) acc += __shfl_down_sync(0xffffffffu, acc, off);
    if (lane == 0) redk[wid] = acc;
    __syncthreads();
    if (tid == 0) {
        float s = 0.0f;
        #pragma unroll
        for (int w = 0; w < NWARP; w++) s += redk[w];
        // single fixed-point atomic: order-invariant integer sum -> deterministic
        unsigned long long add = CNT_ONE + (unsigned long long)__float2ll_rn(s * FIXSCALE);
        unsigned long long old = atomicAdd(&g_accum, add);
        if ((old >> 56) == NROWS - 1) {          // this was the final arrival
            unsigned long long tot = (old + add) & SUM_MASK;
            out[0] = (float)((double)tot * (1.0 / 1099511627776.0));
            g_accum = 0ull;                      // reset for next graph replay
        }
    }
}

extern "C" void kernel_launch(void* const* d_in, const int* in_sizes, int n_in,
                              void* d_out, int out_size) {
    const float* in = (const float*)d_in[0];
    const float* tg = (const float*)d_in[1];
    entropy_fused<<<NROWS, NT>>>(in, tg, (float*)d_out);
}